// round 1
// baseline (speedup 1.0000x reference)
#include <cuda_runtime.h>
#include <cstdint>

// ---------------- problem constants ----------------
#define NNZ      220939
#define CIN      32
#define COUT     64
#define KVOL     27
#define IN_X     21
#define IN_Y     800
#define IN_Z     704
#define OUT_X    11
#define OUT_Y    400
#define OUT_Z    352

// ---------------- device scratch (static, allocation-free) ----------------
// Rulebook: for each of 27 kernel offsets, a list of (input_row, output_flat).
__device__ int2 g_rules[(size_t)KVOL * NNZ];          // 47.7 MB
// Counters, padded 512B apart to spread across L2 slices.
__device__ int  g_cnt[KVOL * 128];

// ---------------- f32x2 helpers ----------------
#define FFMA2(d, a, b, c) \
    asm("fma.rn.f32x2 %0, %1, %2, %3;" : "=l"(d) : "l"(a), "l"(b), "l"(c))

// ---------------- kernel 1: reset counters ----------------
__global__ void reset_counters() {
    int i = threadIdx.x + blockIdx.x * blockDim.x;
    if (i < KVOL * 128) g_cnt[i] = 0;
}

// ---------------- kernel 2: build rulebook (warp-aggregated atomics) ----------
__global__ void build_rules(const int* __restrict__ coords, int n) {
    int i    = blockIdx.x * blockDim.x + threadIdx.x;
    int lane = threadIdx.x & 31;
    bool active = (i < n);

    int cx = 0, cy = 0, cz = 0;
    if (active) {
        cx = coords[i * 3 + 0];
        cy = coords[i * 3 + 1];
        cz = coords[i * 3 + 2];
    }

    // Per-dim validity/quotient for the 3 offsets (pad=1, stride=2).
    bool vX[3], vY[3], vZ[3];
    int  qX[3], qY[3], qZ[3];
#pragma unroll
    for (int o = 0; o < 3; o++) {
        int ox = cx + 1 - o; vX[o] = (ox >= 0) && !(ox & 1) && ((ox >> 1) < OUT_X); qX[o] = ox >> 1;
        int oy = cy + 1 - o; vY[o] = (oy >= 0) && !(oy & 1) && ((oy >> 1) < OUT_Y); qY[o] = oy >> 1;
        int oz = cz + 1 - o; vZ[o] = (oz >= 0) && !(oz & 1) && ((oz >> 1) < OUT_Z); qZ[o] = oz >> 1;
    }

#pragma unroll
    for (int kx = 0; kx < 3; kx++) {
#pragma unroll
        for (int ky = 0; ky < 3; ky++) {
#pragma unroll
            for (int kz = 0; kz < 3; kz++) {
                int k = (kx * 3 + ky) * 3 + kz;
                bool valid = active && vX[kx] && vY[ky] && vZ[kz];
                int flat = 0;
                if (valid) flat = (qX[kx] * OUT_Y + qY[ky]) * OUT_Z + qZ[kz];

                unsigned mask = __ballot_sync(0xffffffffu, valid);
                if (mask) {
                    int leader = __ffs(mask) - 1;
                    int base = 0;
                    if (lane == leader)
                        base = atomicAdd(&g_cnt[k * 128], __popc(mask));
                    base = __shfl_sync(0xffffffffu, base, leader);
                    if (valid) {
                        int pos = base + __popc(mask & ((1u << lane) - 1u));
                        g_rules[(size_t)k * NNZ + pos] = make_int2(i, flat);
                    }
                }
            }
        }
    }
}

// ---------------- kernel 3: gather-GEMM-scatter per offset -------------------
// grid: (TILES_X, 27). block: 256 threads = 4 concurrent points x 64 couts.
// Each thread owns one output channel; its 32-long weight column lives in
// 16 packed f32x2 registers. Features staged in shared, read as broadcast
// ld.shared.v2.u64. Scatter via warp-coalesced RED.ADD.F32 (64 contiguous
// channels per output row).
#define TILE_P  128   // points per tile
#define GROUP_P 16    // points staged per barrier pair

__global__ __launch_bounds__(256, 6)
void gather_gemm_scatter(const float* __restrict__ features,
                         const float* __restrict__ weight,
                         float* __restrict__ out) {
    const int k   = blockIdx.y;
    const int cnt = g_cnt[k * 128];
    if ((int)blockIdx.x * TILE_P >= cnt) return;

    const int tid   = threadIdx.x;
    const int cout  = tid & 63;
    const int pbase = tid >> 6;             // 0..3

    // Pack this thread's weight column W[k][:, cout] into 16 f32x2 regs.
    unsigned long long w2[16];
    {
        const float* wk = weight + (size_t)k * (CIN * COUT) + cout;
#pragma unroll
        for (int q = 0; q < 16; q++) {
            float w0 = wk[(2 * q + 0) * COUT];
            float w1 = wk[(2 * q + 1) * COUT];
            asm("mov.b64 %0, {%1, %2};" : "=l"(w2[q]) : "f"(w0), "f"(w1));
        }
    }

    __shared__ float sf[GROUP_P][CIN];      // 16 x 32 floats, rows 16B aligned
    __shared__ int   sflat[GROUP_P];

    const int2* rules_k = g_rules + (size_t)k * NNZ;

    for (int tile = blockIdx.x; tile * TILE_P < cnt; tile += gridDim.x) {
        const int base = tile * TILE_P;
        for (int g0 = 0; g0 < TILE_P; g0 += GROUP_P) {
            __syncthreads();
            // stage GROUP_P points: 512 floats, 2 per thread
#pragma unroll
            for (int e = tid; e < GROUP_P * CIN; e += 256) {
                int p = e >> 5;             // 0..15
                int c = e & 31;
                int j = base + g0 + p;
                if (j < cnt) {
                    int2 r = rules_k[j];
                    sf[p][c] = features[(size_t)r.x * CIN + c];
                    if (c == 0) sflat[p] = r.y;
                }
            }
            __syncthreads();

#pragma unroll
            for (int pp = 0; pp < GROUP_P; pp += 4) {
                int p = pbase + pp;
                int j = base + g0 + p;
                if (j < cnt) {
                    unsigned long long acc = 0ull;   // (0.0f, 0.0f)
                    const ulonglong2* f2 = (const ulonglong2*)sf[p];
#pragma unroll
                    for (int q = 0; q < 8; q++) {
                        ulonglong2 u = f2[q];
                        FFMA2(acc, u.x, w2[2 * q + 0], acc);
                        FFMA2(acc, u.y, w2[2 * q + 1], acc);
                    }
                    float a0, a1;
                    asm("mov.b64 {%0, %1}, %2;" : "=f"(a0), "=f"(a1) : "l"(acc));
                    atomicAdd(out + (size_t)sflat[p] * COUT + cout, a0 + a1);
                }
            }
        }
    }
}

// ---------------- launch ----------------
extern "C" void kernel_launch(void* const* d_in, const int* in_sizes, int n_in,
                              void* d_out, int out_size) {
    const float* features = (const float*)d_in[0];
    const int*   coords   = (const int*)d_in[1];
    const float* weight   = (const float*)d_in[2];
    float*       out      = (float*)d_out;

    // Dense output: inactive sites must be exactly zero (buffer is poisoned).
    cudaMemsetAsync(out, 0, (size_t)out_size * sizeof(float));

    reset_counters<<<(KVOL * 128 + 255) / 256, 256>>>();

    build_rules<<<(NNZ + 255) / 256, 256>>>(coords, NNZ);

    // ~216 expected tiles per offset (count[k] ~ NNZ/8); 256 gives headroom,
    // and the grid-stride tile loop handles any skew safely up to NNZ.
    dim3 grid((NNZ + TILE_P - 1) / TILE_P < 256 ? (NNZ + TILE_P - 1) / TILE_P : 256, KVOL);
    gather_gemm_scatter<<<grid, 256>>>(features, weight, out);
}